// round 3
// baseline (speedup 1.0000x reference)
#include <cuda_runtime.h>
#include <math.h>
#include <stdint.h>

#define NN    30000
#define EE    480000
#define HIDN  256
#define NLAY  6

// ---------------- static device scratch ----------------
static __device__ __align__(128) float g_hh[2][NN * HIDN];   // h split hi
static __device__ __align__(128) float g_hl[2][NN * HIDN];   // h split lo
static __device__ __align__(128) float g_xl[NN * HIDN];
static __device__ __align__(128) float g_xr[NN * HIDN];
static __device__ __align__(128) float g_t[NN * 128];
static __device__ __align__(128) float g_WTh[(NLAY * 512 + 128) * 256];
static __device__ __align__(128) float g_WTl[(NLAY * 512 + 128) * 256];
static __device__ __align__(128) float g_B[NLAY * 10 * 256];
static __device__ __align__(128) float g_c[NLAY * 256];
static __device__ __align__(128) float g_A[NLAY * 10 * 256];
static __device__ __align__(128) float g_d[NLAY * 256];
static __device__ int g_cnt[NN + 1];
static __device__ int g_start[NN + 1];
static __device__ int g_cursor[NN + 1];
static __device__ int g_eid[EE];

// ---------------- helpers ----------------
__device__ __forceinline__ void split_tf32(float x, float& hi, float& lo) {
    uint32_t u;
    asm("cvt.rna.tf32.f32 %0, %1;" : "=r"(u) : "f"(x));
    float h = __uint_as_float(u);
    float r = x - h;
    uint32_t ul;
    asm("cvt.rna.tf32.f32 %0, %1;" : "=r"(ul) : "f"(r));
    hi = h; lo = __uint_as_float(ul);
}

__device__ __forceinline__ void mma_tf32(float* d, const uint32_t* a, const uint32_t* b) {
    asm volatile(
        "mma.sync.aligned.m16n8k8.row.col.f32.tf32.tf32.f32 "
        "{%0,%1,%2,%3}, {%4,%5,%6,%7}, {%8,%9}, {%0,%1,%2,%3};"
        : "+f"(d[0]), "+f"(d[1]), "+f"(d[2]), "+f"(d[3])
        : "r"(a[0]), "r"(a[1]), "r"(a[2]), "r"(a[3]), "r"(b[0]), "r"(b[1]));
}

// ---------------- CSR build ----------------
__global__ void zero_kernel() {
    int i = blockIdx.x * 256 + threadIdx.x;
    if (i <= NN) g_cnt[i] = 0;
}
__global__ void count_kernel(const int* __restrict__ dst) {
    int e = blockIdx.x * 256 + threadIdx.x;
    if (e < EE) atomicAdd(&g_cnt[dst[e]], 1);
}
__global__ void scan_kernel() {
    __shared__ int part[1024];
    const int T = 1024, ITEMS = (NN + T - 1) / T;
    int tid = threadIdx.x, base = tid * ITEMS, s = 0;
    for (int i = 0; i < ITEMS; ++i) { int idx = base + i; if (idx < NN) s += g_cnt[idx]; }
    part[tid] = s;
    __syncthreads();
    for (int off = 1; off < T; off <<= 1) {
        int v = 0;
        if (tid >= off) v = part[tid - off];
        __syncthreads();
        part[tid] += v;
        __syncthreads();
    }
    int run = (tid == 0) ? 0 : part[tid - 1];
    for (int i = 0; i < ITEMS; ++i) {
        int idx = base + i;
        if (idx < NN) { g_start[idx] = run; g_cursor[idx] = run; run += g_cnt[idx]; }
    }
    if (tid == T - 1) g_start[NN] = part[T - 1];
}
__global__ void fill_kernel(const int* __restrict__ dst) {
    int e = blockIdx.x * 256 + threadIdx.x;
    if (e < EE) { int pos = atomicAdd(&g_cursor[dst[e]], 1); g_eid[pos] = e; }
}
__global__ void sort_kernel() {
    int n = blockIdx.x * 256 + threadIdx.x;
    if (n >= NN) return;
    int s0 = g_start[n], s1 = g_start[n + 1];
    for (int i = s0 + 1; i < s1; ++i) {
        int v = g_eid[i]; int j = i - 1;
        while (j >= s0 && g_eid[j] > v) { g_eid[j + 1] = g_eid[j]; --j; }
        g_eid[j + 1] = v;
    }
}

// ---------------- edge-matrix chain precompute ----------------
__global__ void chain_kernel(const float* __restrict__ eW, const float* __restrict__ eb,
                             const float* __restrict__ Weu, const float* __restrict__ beu) {
    __shared__ float Ash[10 * 256];
    __shared__ float dsh[256];
    int tid = threadIdx.x;
    for (int t = tid; t < 2560; t += 256) Ash[t] = eW[t];
    dsh[tid] = eb[tid];
    __syncthreads();
    for (int i = 0; i < NLAY; ++i) {
        for (int t = tid; t < 2560; t += 256) g_A[i * 2560 + t] = Ash[t];
        g_d[i * 256 + tid] = dsh[tid];
        __syncthreads();
        if (i == NLAY - 1) break;
        const float* Wp = Weu + (size_t)i * 65536;
        float accA[10];
        #pragma unroll
        for (int k = 0; k < 10; ++k) accA[k] = 0.f;
        float accd = 0.f;
        for (int c = 0; c < 256; ++c) {
            float w = Wp[c * 256 + tid];
            accd = fmaf(dsh[c], w, accd);
            #pragma unroll
            for (int k = 0; k < 10; ++k) accA[k] = fmaf(Ash[k * 256 + c], w, accA[k]);
        }
        accd += beu[i * 256 + tid];
        __syncthreads();
        #pragma unroll
        for (int k = 0; k < 10; ++k) Ash[k * 256 + tid] = accA[k];
        dsh[tid] = accd;
        __syncthreads();
    }
}
__global__ void bmat_kernel(const float* __restrict__ We) {
    __shared__ float Ash[10 * 256];
    __shared__ float dsh[256];
    int i = blockIdx.x, tid = threadIdx.x;
    for (int t = tid; t < 2560; t += 256) Ash[t] = g_A[i * 2560 + t];
    dsh[tid] = g_d[i * 256 + tid];
    __syncthreads();
    const float* Wp = We + (size_t)i * 65536;
    float accB[10];
    #pragma unroll
    for (int k = 0; k < 10; ++k) accB[k] = 0.f;
    float accc = 0.f;
    for (int c = 0; c < 256; ++c) {
        float w = Wp[c * 256 + tid];
        accc = fmaf(dsh[c], w, accc);
        #pragma unroll
        for (int k = 0; k < 10; ++k) accB[k] = fmaf(Ash[k * 256 + c], w, accB[k]);
    }
    #pragma unroll
    for (int k = 0; k < 10; ++k) g_B[i * 2560 + k * 256 + tid] = accB[k];
    g_c[i * 256 + tid] = accc;
}

// ---------------- weight transpose + tf32 split ----------------
// g_WT{h,l}[row][k] with row = output column (n), k contiguous. Rows 0..NLAY*512-1
// are per-layer [Wl^T | Wr^T]; the last 128 rows are out_W1^T.
__global__ void wprep_kernel(const float* __restrict__ Wl, const float* __restrict__ Wr,
                             const float* __restrict__ oW1) {
    int idx = blockIdx.x * 256 + threadIdx.x;
    const int LTOT = NLAY * 512 * 256;   // 786432
    float v;
    if (idx < LTOT) {
        int l = idx >> 17;
        int rem = idx & 131071;
        int row = rem >> 8, k = rem & 255;
        v = (row < 256) ? Wl[(size_t)l * 65536 + k * 256 + row]
                        : Wr[(size_t)l * 65536 + k * 256 + (row - 256)];
    } else if (idx < LTOT + 128 * 256) {
        int rem = idx - LTOT;
        int row = rem >> 8, k = rem & 255;
        v = oW1[k * 128 + row];
    } else return;
    float hi, lo;
    split_tf32(v, hi, lo);
    g_WTh[idx] = hi; g_WTl[idx] = lo;
}

// ---------------- node encoder ----------------
__global__ void encoder_kernel(const float* __restrict__ x, const float* __restrict__ nW,
                               const float* __restrict__ nb) {
    int idx = blockIdx.x * 256 + threadIdx.x;
    int n = idx >> 8, c = idx & 255;
    if (n >= NN) return;
    float s = nb[c];
    #pragma unroll
    for (int k = 0; k < 13; ++k) s = fmaf(x[n * 13 + k], nW[k * 256 + c], s);
    float hi, lo;
    split_tf32(s, hi, lo);
    g_hh[0][idx] = hi; g_hl[0][idx] = lo;
}

// ---------------- 3xTF32 mma.sync GEMM ----------------
// C[128 x 128-per-colblock] = h[hsel] @ WT^T (+bias, leaky slope).
// 256 threads = 8 warps (2 m x 4 n), warp tile 64x32, mma m16n8k8.
// Shared tiles stored operand-natural with row stride 36 floats -> fragment
// LDS bank index == lane (conflict-free), no transposes anywhere.
#define AOFF_L 4608
#define BOFF_H 9216
#define BOFF_L 13824
#define SMEM_FLOATS 18432
#define SMEM_BYTES  (SMEM_FLOATS * 4)

__global__ __launch_bounds__(256, 1)
void mma_gemm(int hsel, int wrow0, const float* __restrict__ bias0,
              const float* __restrict__ bias1, int outmode, float slope) {
    extern __shared__ __align__(16) float sm[];
    const float* __restrict__ Ah = g_hh[hsel];
    const float* __restrict__ Al = g_hl[hsel];

    int tid = threadIdx.x;
    int wid = tid >> 5, lane = tid & 31;
    int warp_m = wid & 1, warp_n = wid >> 1;
    int m0 = blockIdx.x * 128;
    int colg = blockIdx.y * 128;

    float c[4][4][4];
    #pragma unroll
    for (int mi = 0; mi < 4; ++mi)
        #pragma unroll
        for (int ni = 0; ni < 4; ++ni)
            #pragma unroll
            for (int j = 0; j < 4; ++j) c[mi][ni][j] = 0.f;

    int row = lane >> 2, kq4 = lane & 3;

    for (int it = 0; it < 8; ++it) {
        int kt = it * 32;
        // A tiles: 128 rows x 32 k, hi+lo
        #pragma unroll
        for (int i = 0; i < 4; ++i) {
            int slot = tid + i * 256;
            int m = slot >> 3, kq = slot & 7;
            int gm = m0 + m;
            float4 vh = make_float4(0.f, 0.f, 0.f, 0.f), vl = vh;
            if (gm < NN) {
                vh = *(const float4*)(Ah + (size_t)gm * 256 + kt + kq * 4);
                vl = *(const float4*)(Al + (size_t)gm * 256 + kt + kq * 4);
            }
            *(float4*)(sm + m * 36 + kq * 4) = vh;
            *(float4*)(sm + AOFF_L + m * 36 + kq * 4) = vl;
        }
        // B tiles: 128 n-rows x 32 k, hi+lo
        #pragma unroll
        for (int i = 0; i < 4; ++i) {
            int slot = tid + i * 256;
            int n = slot >> 3, kq = slot & 7;
            size_t src = (size_t)(wrow0 + colg + n) * 256 + kt + kq * 4;
            *(float4*)(sm + BOFF_H + n * 36 + kq * 4) = *(const float4*)(g_WTh + src);
            *(float4*)(sm + BOFF_L + n * 36 + kq * 4) = *(const float4*)(g_WTl + src);
        }
        __syncthreads();

        const uint32_t* As_h = (const uint32_t*)sm;
        const uint32_t* As_l = (const uint32_t*)(sm + AOFF_L);
        const uint32_t* Bs_h = (const uint32_t*)(sm + BOFF_H);
        const uint32_t* Bs_l = (const uint32_t*)(sm + BOFF_L);

        #pragma unroll
        for (int ks = 0; ks < 4; ++ks) {
            int k0 = ks * 8;
            uint32_t ah[4][4], al[4][4], bh[4][2], bl[4][2];
            #pragma unroll
            for (int mi = 0; mi < 4; ++mi) {
                int base = (warp_m * 64 + mi * 16 + row) * 36 + k0 + kq4;
                ah[mi][0] = As_h[base];
                ah[mi][1] = As_h[base + 8 * 36];
                ah[mi][2] = As_h[base + 4];
                ah[mi][3] = As_h[base + 8 * 36 + 4];
                al[mi][0] = As_l[base];
                al[mi][1] = As_l[base + 8 * 36];
                al[mi][2] = As_l[base + 4];
                al[mi][3] = As_l[base + 8 * 36 + 4];
            }
            #pragma unroll
            for (int ni = 0; ni < 4; ++ni) {
                int base = (warp_n * 32 + ni * 8 + row) * 36 + k0 + kq4;
                bh[ni][0] = Bs_h[base];
                bh[ni][1] = Bs_h[base + 4];
                bl[ni][0] = Bs_l[base];
                bl[ni][1] = Bs_l[base + 4];
            }
            #pragma unroll
            for (int mi = 0; mi < 4; ++mi)
                #pragma unroll
                for (int ni = 0; ni < 4; ++ni) {
                    mma_tf32(c[mi][ni], ah[mi], bh[ni]);
                    mma_tf32(c[mi][ni], ah[mi], bl[ni]);
                    mma_tf32(c[mi][ni], al[mi], bh[ni]);
                }
        }
        __syncthreads();
    }

    // epilogue: bias + leaky, route to g_xl / g_xr / g_t
    #pragma unroll
    for (int mi = 0; mi < 4; ++mi) {
        #pragma unroll
        for (int ni = 0; ni < 4; ++ni) {
            int gn = colg + warp_n * 32 + ni * 8 + (lane & 3) * 2;
            float* outp; const float* bp; int cc, ld;
            if (outmode)        { outp = g_t;  bp = bias0; cc = gn;        ld = 128; }
            else if (gn < 256)  { outp = g_xl; bp = bias0; cc = gn;        ld = 256; }
            else                { outp = g_xr; bp = bias1; cc = gn - 256;  ld = 256; }
            float b0v = bp[cc], b1v = bp[cc + 1];
            int gm = m0 + warp_m * 64 + mi * 16 + (lane >> 2);
            if (gm < NN) {
                float v0 = c[mi][ni][0] + b0v; v0 = v0 >= 0.f ? v0 : slope * v0;
                float v1 = c[mi][ni][1] + b1v; v1 = v1 >= 0.f ? v1 : slope * v1;
                *(float2*)(outp + (size_t)gm * ld + cc) = make_float2(v0, v1);
            }
            int gm2 = gm + 8;
            if (gm2 < NN) {
                float v0 = c[mi][ni][2] + b0v; v0 = v0 >= 0.f ? v0 : slope * v0;
                float v1 = c[mi][ni][3] + b1v; v1 = v1 >= 0.f ? v1 : slope * v1;
                *(float2*)(outp + (size_t)gm2 * ld + cc) = make_float2(v0, v1);
            }
        }
    }
}

// ---------------- fused GATv2 attention + BN + leaky + residual ----------------
__global__ void attn_kernel(int layer, int hin,
                            const float* __restrict__ att, const float* __restrict__ conv_b,
                            const float* __restrict__ bng, const float* __restrict__ bnb,
                            const float* __restrict__ bnrm, const float* __restrict__ bnrv,
                            const int* __restrict__ src_arr,
                            const float* __restrict__ eattr) {
    __shared__ float Bsh[2560];
    __shared__ float csh[256];
    __shared__ float attsh[256];
    __shared__ float cbsh[256];
    __shared__ float scsh[256];
    __shared__ float shsh[256];
    int tid = threadIdx.x;
    for (int t = tid; t < 2560; t += 256) Bsh[t] = g_B[layer * 2560 + t];
    {
        int c = tid;
        csh[c]   = g_c[layer * 256 + c];
        attsh[c] = att[layer * 256 + c];
        cbsh[c]  = conv_b[layer * 256 + c];
        float sc = bng[layer * 256 + c] * rsqrtf(bnrv[layer * 256 + c] + 1e-5f);
        scsh[c]  = sc;
        shsh[c]  = bnb[layer * 256 + c] - bnrm[layer * 256 + c] * sc;
    }
    __syncthreads();

    int warp = tid >> 5, lane = tid & 31;
    int n = blockIdx.x * 8 + warp;
    if (n >= NN) return;
    int hout = hin ^ 1;

    float xr8[8], mh[8], ssum[8], accv[8];
    #pragma unroll
    for (int h = 0; h < 8; ++h) {
        xr8[h] = g_xr[n * 256 + h * 32 + lane];
        mh[h] = -INFINITY; ssum[h] = 0.f; accv[h] = 0.f;
    }

    int s0 = g_start[n], s1 = g_start[n + 1];
    for (int p = s0; p < s1; ++p) {
        int e = g_eid[p];
        int sn = src_arr[e];
        float eav = (lane < 10) ? eattr[e * 10 + lane] : 0.f;
        float xls[8], val[8];
        #pragma unroll
        for (int h = 0; h < 8; ++h) {
            xls[h] = g_xl[sn * 256 + h * 32 + lane];
            val[h] = csh[h * 32 + lane];
        }
        #pragma unroll
        for (int k = 0; k < 10; ++k) {
            float a = __shfl_sync(0xffffffffu, eav, k);
            #pragma unroll
            for (int h = 0; h < 8; ++h)
                val[h] = fmaf(a, Bsh[k * 256 + h * 32 + lane], val[h]);
        }
        #pragma unroll
        for (int h = 0; h < 8; ++h) {
            float v = xls[h] + xr8[h] + val[h];
            v = v >= 0.f ? v : 0.2f * v;
            val[h] = v * attsh[h * 32 + lane];
        }
        #pragma unroll
        for (int off = 16; off > 0; off >>= 1) {
            #pragma unroll
            for (int h = 0; h < 8; ++h)
                val[h] += __shfl_xor_sync(0xffffffffu, val[h], off);
        }
        #pragma unroll
        for (int h = 0; h < 8; ++h) {
            float L = val[h];
            float nm = fmaxf(mh[h], L);
            float f = __expf(mh[h] - nm);
            float w = __expf(L - nm);
            ssum[h] = ssum[h] * f + w;
            accv[h] = accv[h] * f + w * xls[h];
            mh[h] = nm;
        }
    }

    #pragma unroll
    for (int h = 0; h < 8; ++h) {
        int c = h * 32 + lane;
        float agg = accv[h] / (ssum[h] + 1e-16f);
        float v = agg + cbsh[c];
        v = v * scsh[c] + shsh[c];
        v = v >= 0.f ? v : 0.01f * v;
        if (layer >= 1) v += g_hh[hin][n * 256 + c] + g_hl[hin][n * 256 + c];
        float hi, lo;
        split_tf32(v, hi, lo);
        g_hh[hout][n * 256 + c] = hi;
        g_hl[hout][n * 256 + c] = lo;
    }
}

// ---------------- head: out = t @ W2 + b2 ----------------
__global__ void head2_kernel(const float* __restrict__ W2, const float* __restrict__ b2,
                             float* __restrict__ out) {
    __shared__ float w[128];
    int tid = threadIdx.x;
    if (tid < 128) w[tid] = W2[tid];
    __syncthreads();
    int n = blockIdx.x * 256 + tid;
    if (n >= NN) return;
    float s = b2[0];
    const float* tp = g_t + (size_t)n * 128;
    #pragma unroll
    for (int j = 0; j < 128; ++j) s = fmaf(tp[j], w[j], s);
    out[n] = s;
}

// ---------------- launch ----------------
extern "C" void kernel_launch(void* const* d_in, const int* in_sizes, int n_in,
                              void* d_out, int out_size) {
    const float* x      = (const float*)d_in[0];
    const int*   ei     = (const int*)d_in[1];
    const float* eattr  = (const float*)d_in[2];
    const float* nW     = (const float*)d_in[3];
    const float* nb     = (const float*)d_in[4];
    const float* eW     = (const float*)d_in[5];
    const float* eb     = (const float*)d_in[6];
    const float* Wl     = (const float*)d_in[7];
    const float* bl     = (const float*)d_in[8];
    const float* Wr     = (const float*)d_in[9];
    const float* br     = (const float*)d_in[10];
    const float* We     = (const float*)d_in[11];
    const float* att    = (const float*)d_in[12];
    const float* conv_b = (const float*)d_in[13];
    const float* Weu    = (const float*)d_in[14];
    const float* beu    = (const float*)d_in[15];
    const float* bng    = (const float*)d_in[16];
    const float* bnb    = (const float*)d_in[17];
    const float* bnrm   = (const float*)d_in[18];
    const float* bnrv   = (const float*)d_in[19];
    const float* oW1    = (const float*)d_in[20];
    const float* ob1    = (const float*)d_in[21];
    const float* oW2    = (const float*)d_in[22];
    const float* ob2    = (const float*)d_in[23];

    const int* srcp = ei;
    const int* dstp = ei + EE;

    cudaFuncSetAttribute(mma_gemm, cudaFuncAttributeMaxDynamicSharedMemorySize, SMEM_BYTES);

    // CSR build (deterministic)
    zero_kernel<<<(NN + 256) / 256, 256>>>();
    count_kernel<<<(EE + 255) / 256, 256>>>(dstp);
    scan_kernel<<<1, 1024>>>();
    fill_kernel<<<(EE + 255) / 256, 256>>>(dstp);
    sort_kernel<<<(NN + 255) / 256, 256>>>();

    // edge matrix chain + weight prep
    chain_kernel<<<1, 256>>>(eW, eb, Weu, beu);
    bmat_kernel<<<NLAY, 256>>>(We);
    wprep_kernel<<<3200, 256>>>(Wl, Wr, oW1);

    // node encoder
    encoder_kernel<<<NN, 256>>>(x, nW, nb);

    const int MT = (NN + 127) / 128;   // 235
    dim3 gemm_grid(MT, 4);
    dim3 head_grid(MT, 1);
    int cur = 0;
    for (int i = 0; i < NLAY; ++i) {
        mma_gemm<<<gemm_grid, 256, SMEM_BYTES>>>(cur, i * 512, bl + i * 256, br + i * 256,
                                                 /*outmode=*/0, /*slope=*/1.0f);
        attn_kernel<<<(NN + 7) / 8, 256>>>(i, cur, att, conv_b, bng, bnb, bnrm, bnrv,
                                           srcp, eattr);
        cur ^= 1;
    }

    // output head
    mma_gemm<<<head_grid, 256, SMEM_BYTES>>>(cur, NLAY * 512, ob1, (const float*)0,
                                             /*outmode=*/1, /*slope=*/0.01f);
    head2_kernel<<<(NN + 255) / 256, 256>>>(oW2, ob2, (float*)d_out);
}